// round 1
// baseline (speedup 1.0000x reference)
#include <cuda_runtime.h>
#include <math.h>

#define BB 4
#define LL 2048
#define DD 512
#define NROW (BB*LL)

// ---- scratch (static device memory; no allocations anywhere) ----
__device__ float g_xact[NROW*DD];   // tanh(x)          16 MB
__device__ float g_stat[NROW*DD];   // x_act @ W^T      16 MB
__device__ float g_odyn[NROW*DD];   // scan output      16 MB
__device__ float g_kk[NROW];        // per-row k.k

// ============================================================
// 1) prep: x_act = tanh(x), kk[row] = sum(x_act^2)
//    one 128-thread block per row (512 floats = 128 x float4)
// ============================================================
__global__ void prep_kernel(const float* __restrict__ x) {
    int row = blockIdx.x;
    int t = threadIdx.x;
    const float4* xin = reinterpret_cast<const float4*>(x + (size_t)row * DD);
    float4* xo = reinterpret_cast<float4*>(g_xact + (size_t)row * DD);
    float4 v = xin[t];
    float4 a;
    a.x = tanhf(v.x); a.y = tanhf(v.y); a.z = tanhf(v.z); a.w = tanhf(v.w);
    xo[t] = a;
    float ss = a.x*a.x + a.y*a.y + a.z*a.z + a.w*a.w;
    __shared__ float red[4];
    #pragma unroll
    for (int o = 16; o > 0; o >>= 1) ss += __shfl_xor_sync(0xffffffffu, ss, o);
    if ((t & 31) == 0) red[t >> 5] = ss;
    __syncthreads();
    if (t == 0) g_kk[row] = red[0] + red[1] + red[2] + red[3];
}

// ============================================================
// 2) SGEMM: g_stat[m,n] = sum_d g_xact[m,d] * W[n,d]
//    (both operands K-contiguous, "NT" dot-product GEMM)
//    128x128 tile, BK=8, 256 threads, 8x8 microtile
// ============================================================
#define BM 128
#define BN 128
#define BK 8

__global__ __launch_bounds__(256) void gemm_kernel(const float* __restrict__ W) {
    __shared__ float As[BK][BM];
    __shared__ float Bs[BK][BN];
    int tid = threadIdx.x;
    int bn = blockIdx.x;   // 0..3
    int bm = blockIdx.y;   // 0..63

    int lr = tid >> 1;            // 0..127 (row within tile)
    int lc = (tid & 1) * 4;       // 0 or 4 (k offset, float4)
    const float* Ag = g_xact + ((size_t)bm * BM + lr) * DD + lc;
    const float* Bg = W      + ((size_t)bn * BN + lr) * DD + lc;

    int tx = tid & 15, ty = tid >> 4;
    int r0 = ty * 8, c0 = tx * 8;

    float acc[8][8];
    #pragma unroll
    for (int i = 0; i < 8; i++)
        #pragma unroll
        for (int j = 0; j < 8; j++) acc[i][j] = 0.f;

    for (int k0 = 0; k0 < DD; k0 += BK) {
        float4 av = *reinterpret_cast<const float4*>(Ag + k0);
        float4 bv = *reinterpret_cast<const float4*>(Bg + k0);
        As[lc + 0][lr] = av.x; As[lc + 1][lr] = av.y;
        As[lc + 2][lr] = av.z; As[lc + 3][lr] = av.w;
        Bs[lc + 0][lr] = bv.x; Bs[lc + 1][lr] = bv.y;
        Bs[lc + 2][lr] = bv.z; Bs[lc + 3][lr] = bv.w;
        __syncthreads();
        #pragma unroll
        for (int k = 0; k < BK; k++) {
            float a[8], b[8];
            float4 a0 = *reinterpret_cast<const float4*>(&As[k][r0]);
            float4 a1 = *reinterpret_cast<const float4*>(&As[k][r0 + 4]);
            float4 b0 = *reinterpret_cast<const float4*>(&Bs[k][c0]);
            float4 b1 = *reinterpret_cast<const float4*>(&Bs[k][c0 + 4]);
            a[0]=a0.x; a[1]=a0.y; a[2]=a0.z; a[3]=a0.w;
            a[4]=a1.x; a[5]=a1.y; a[6]=a1.z; a[7]=a1.w;
            b[0]=b0.x; b[1]=b0.y; b[2]=b0.z; b[3]=b0.w;
            b[4]=b1.x; b[5]=b1.y; b[6]=b1.z; b[7]=b1.w;
            #pragma unroll
            for (int i = 0; i < 8; i++)
                #pragma unroll
                for (int j = 0; j < 8; j++)
                    acc[i][j] = fmaf(a[i], b[j], acc[i][j]);
        }
        __syncthreads();
    }

    #pragma unroll
    for (int i = 0; i < 8; i++) {
        float* cp = g_stat + ((size_t)bm * BM + r0 + i) * DD + bn * BN + c0;
        float4 v0, v1;
        v0.x=acc[i][0]; v0.y=acc[i][1]; v0.z=acc[i][2]; v0.w=acc[i][3];
        v1.x=acc[i][4]; v1.y=acc[i][5]; v1.z=acc[i][6]; v1.w=acc[i][7];
        *reinterpret_cast<float4*>(cp)     = v0;
        *reinterpret_cast<float4*>(cp + 4) = v1;
    }
}

// ============================================================
// 3) scan: gated delta rule, column-sharded.
//    Each 16-lane group owns one v-column of S (512 floats = 32 regs/lane).
//    Chunk-rescaled state S' = S / lam^j  (rescale by lam^64 every 64 steps):
//      d      = k^T S'                     (raw dot, reduce over 16 lanes)
//      verr   = beta * (v - lam^j * d)
//      o      = lam^j * d + (k.k) * verr
//      S'    += k * (lam^{-j} * verr)
//    No barriers, no SMEM; k_t broadcast-loaded, next step prefetched.
// ============================================================
__global__ __launch_bounds__(128) void scan_kernel(const float* __restrict__ eta_p,
                                                   const float* __restrict__ laml_p) {
    float beta = eta_p[0];
    float lam = 1.0f / (1.0f + expf(-laml_p[0]));
    float invlam = 1.0f / lam;
    float lam64 = lam;
    #pragma unroll
    for (int i = 0; i < 6; i++) lam64 *= lam64;   // lam^64 by squaring

    int b    = blockIdx.y;
    int warp = threadIdx.x >> 5;
    int lane = threadIdx.x & 31;
    int g    = lane >> 4;         // half-warp group
    int s    = lane & 15;         // lane within group
    int col  = (blockIdx.x << 3) + (warp << 1) + g;   // 0..511

    const float*  xb = g_xact + (size_t)b * LL * DD;
    const float*  vb = g_stat + (size_t)b * LL * DD + col;
    const float*  kb = g_kk   + (size_t)b * LL;
    float*        ob = g_odyn + (size_t)b * LL * DD + col;

    // state: rows 4*(s+16j)+m for j=0..7, m=0..3  (covers all 512 rows per group)
    float S[32];
    #pragma unroll
    for (int i = 0; i < 32; i++) S[i] = 0.f;

    float4 kc[8];
    {
        const float4* kp = reinterpret_cast<const float4*>(xb);
        #pragma unroll
        for (int j = 0; j < 8; j++) kc[j] = kp[s + 16 * j];
    }
    float vv  = vb[0];
    float kkv = kb[0];

    float p = lam, pinv = invlam;

    for (int t = 0; t < LL; t++) {
        // prefetch next step's operands (hide LDG latency under the math)
        int tn = (t + 1 < LL) ? (t + 1) : t;
        float4 kn[8];
        {
            const float4* kpn = reinterpret_cast<const float4*>(xb + (size_t)tn * DD);
            #pragma unroll
            for (int j = 0; j < 8; j++) kn[j] = kpn[s + 16 * j];
        }
        float vn  = vb[(size_t)tn * DD];
        float kkn = kb[tn];

        // dot: d = k^T S'   (4 independent accumulator chains)
        float a0 = 0.f, a1 = 0.f, a2 = 0.f, a3 = 0.f;
        #pragma unroll
        for (int j = 0; j < 8; j++) {
            a0 = fmaf(kc[j].x, S[4*j+0], a0);
            a1 = fmaf(kc[j].y, S[4*j+1], a1);
            a2 = fmaf(kc[j].z, S[4*j+2], a2);
            a3 = fmaf(kc[j].w, S[4*j+3], a3);
        }
        float d = (a0 + a1) + (a2 + a3);
        d += __shfl_xor_sync(0xffffffffu, d, 1);
        d += __shfl_xor_sync(0xffffffffu, d, 2);
        d += __shfl_xor_sync(0xffffffffu, d, 4);
        d += __shfl_xor_sync(0xffffffffu, d, 8);

        float pd   = p * d;
        float verr = beta * (vv - pd);
        float o    = pd + kkv * verr;
        if (s == 0) ob[(size_t)t * DD] = o;

        float w = pinv * verr;
        #pragma unroll
        for (int j = 0; j < 8; j++) {
            S[4*j+0] = fmaf(kc[j].x, w, S[4*j+0]);
            S[4*j+1] = fmaf(kc[j].y, w, S[4*j+1]);
            S[4*j+2] = fmaf(kc[j].z, w, S[4*j+2]);
            S[4*j+3] = fmaf(kc[j].w, w, S[4*j+3]);
        }

        if ((t & 63) == 63) {
            // chunk boundary: S <- lam^64 * S', reset powers
            #pragma unroll
            for (int i = 0; i < 32; i++) S[i] *= lam64;
            p = lam; pinv = invlam;
        } else {
            p *= lam; pinv *= invlam;
        }

        #pragma unroll
        for (int j = 0; j < 8; j++) kc[j] = kn[j];
        vv = vn; kkv = kkn;
    }
}

// ============================================================
// 4) LayerNorm: y = stat + odyn; normalize over D; gamma/beta
//    one 128-thread block per row
// ============================================================
__global__ void ln_kernel(const float* __restrict__ gamma,
                          const float* __restrict__ lbeta,
                          float* __restrict__ out) {
    int row = blockIdx.x;
    int t = threadIdx.x;
    const float4* sp = reinterpret_cast<const float4*>(g_stat + (size_t)row * DD);
    const float4* op = reinterpret_cast<const float4*>(g_odyn + (size_t)row * DD);
    float4 sv = sp[t], ov = op[t];
    float4 y;
    y.x = sv.x + ov.x; y.y = sv.y + ov.y; y.z = sv.z + ov.z; y.w = sv.w + ov.w;

    float sum = y.x + y.y + y.z + y.w;
    float sq  = y.x*y.x + y.y*y.y + y.z*y.z + y.w*y.w;

    __shared__ float r1[4], r2[4];
    #pragma unroll
    for (int o = 16; o > 0; o >>= 1) {
        sum += __shfl_xor_sync(0xffffffffu, sum, o);
        sq  += __shfl_xor_sync(0xffffffffu, sq, o);
    }
    if ((t & 31) == 0) { r1[t >> 5] = sum; r2[t >> 5] = sq; }
    __syncthreads();
    __shared__ float smu, srs;
    if (t == 0) {
        float ts = r1[0] + r1[1] + r1[2] + r1[3];
        float tq = r2[0] + r2[1] + r2[2] + r2[3];
        float mu = ts * (1.0f / DD);
        float var = tq * (1.0f / DD) - mu * mu;
        smu = mu;
        srs = rsqrtf(var + 1e-5f);
    }
    __syncthreads();
    float mu = smu, rs = srs;

    const float4* gp = reinterpret_cast<const float4*>(gamma);
    const float4* bp = reinterpret_cast<const float4*>(lbeta);
    float4 gv = gp[t], bv = bp[t];
    float4 r;
    r.x = (y.x - mu) * rs * gv.x + bv.x;
    r.y = (y.y - mu) * rs * gv.y + bv.y;
    r.z = (y.z - mu) * rs * gv.z + bv.z;
    r.w = (y.w - mu) * rs * gv.w + bv.w;
    reinterpret_cast<float4*>(out + (size_t)row * DD)[t] = r;
}

// ============================================================
extern "C" void kernel_launch(void* const* d_in, const int* in_sizes, int n_in,
                              void* d_out, int out_size) {
    const float* x     = (const float*)d_in[0];
    const float* W     = (const float*)d_in[1];
    const float* eta   = (const float*)d_in[2];
    const float* laml  = (const float*)d_in[3];
    const float* gamma = (const float*)d_in[4];
    const float* lbeta = (const float*)d_in[5];
    float* out = (float*)d_out;

    prep_kernel<<<NROW, 128>>>(x);
    gemm_kernel<<<dim3(DD / BN, NROW / BM), 256>>>(W);
    scan_kernel<<<dim3(DD / 8, BB), 128>>>(eta, laml);
    ln_kernel<<<NROW, 128>>>(gamma, lbeta, out);
}